// round 1
// baseline (speedup 1.0000x reference)
#include <cuda_runtime.h>
#include <cstdint>

// 2-layer LSTM (HID=10), B=2048, T=1024, future=64.
// Layout: 10 lanes per batch element, 3 elements per warp (lanes 30,31 idle-mirror).
// Each lane owns one hidden unit (its 4 gate rows) for both layers.
// h1/h2 vectors exchanged through per-warp shared memory, read back as float4
// so f32x2 packed FMAs get naturally-paired operands.
// Sigmoid/tanh via ex2.approx + rcp.approx with -log2e / -2log2e pre-folded
// into the weights/biases (no extra scaling MULs at runtime).

#define HID 10

typedef unsigned long long u64;

__device__ __forceinline__ u64 pk(float a, float b) {
    u64 r; asm("mov.b64 %0, {%1, %2};" : "=l"(r) : "f"(a), "f"(b)); return r;
}
__device__ __forceinline__ float2 upk(u64 v) {
    float2 f; asm("mov.b64 {%0, %1}, %2;" : "=f"(f.x), "=f"(f.y) : "l"(v)); return f;
}
__device__ __forceinline__ u64 ffma2(u64 a, u64 b, u64 c) {
    u64 d; asm("fma.rn.f32x2 %0, %1, %2, %3;" : "=l"(d) : "l"(a), "l"(b), "l"(c)); return d;
}
__device__ __forceinline__ float hsum(u64 v) { float2 f = upk(v); return f.x + f.y; }

__device__ __forceinline__ float fast_ex2(float x) {
    float r; asm("ex2.approx.f32 %0, %1;" : "=f"(r) : "f"(x)); return r;
}
__device__ __forceinline__ float fast_rcp(float x) {
    float r; asm("rcp.approx.f32 %0, %1;" : "=f"(r) : "f"(x)); return r;
}
// A is already -z*log2e : sigmoid(z)
__device__ __forceinline__ float sig_scaled(float A) {
    return fast_rcp(1.0f + fast_ex2(A));
}
// A is already -2z*log2e : tanh(z) = 2*sigmoid(2z) - 1
__device__ __forceinline__ float tanh_scaled(float A) {
    return fmaf(fast_rcp(1.0f + fast_ex2(A)), 2.0f, -1.0f);
}
__device__ __forceinline__ float tanh_plain(float c) {
    return tanh_scaled(c * -2.885390081777927f);  // -2*log2(e)
}

__global__ void __launch_bounds__(32, 1)
lstm2_kernel(const float* __restrict__ x,
             const float* __restrict__ Wih1, const float* __restrict__ Whh1,
             const float* __restrict__ bih1, const float* __restrict__ bhh1,
             const float* __restrict__ Wih2, const float* __restrict__ Whh2,
             const float* __restrict__ bih2, const float* __restrict__ bhh2,
             const float* __restrict__ Wlin, const float* __restrict__ blin,
             float* __restrict__ out,
             int B, int T, int TT)
{
    const int lane = threadIdx.x;
    int e = lane / HID;                 // element slot within warp: 0..2 (3 = idle lanes)
    int u = lane - e * HID;             // hidden unit owned by this lane
    const bool lane_ok = (e < 3);
    const int ec = lane_ok ? e : 2;     // idle lanes mirror element slot 2
    const int b = blockIdx.x * 3 + ec;
    const bool b_ok = lane_ok && (b < B);
    const int bc = (b < B) ? b : (B - 1);

    // ---- load + pre-scale weights into registers (one-time) ----
    const float NL  = -1.4426950408889634f;   // -log2(e)   (i, f, o: sigmoid)
    const float N2L = -2.885390081777927f;    // -2*log2(e) (g: tanh)
    const float scl[4] = {NL, NL, N2L, NL};

    u64 Whh1r[4][5], Wih2r[4][5], Whh2r[4][5];
    float bias1[4], bias2[4], wx1[4];
#pragma unroll
    for (int g = 0; g < 4; ++g) {
        const float s = scl[g];
        const int r = g * HID + u;
        bias1[g] = (__ldg(&bih1[r]) + __ldg(&bhh1[r])) * s;
        bias2[g] = (__ldg(&bih2[r]) + __ldg(&bhh2[r])) * s;
        wx1[g]   = __ldg(&Wih1[r]) * s;        // W_ih1 is [40,1]
#pragma unroll
        for (int p = 0; p < 5; ++p) {
            float2 w;
            w = *(const float2*)&Whh1[r * HID + 2 * p]; Whh1r[g][p] = pk(w.x * s, w.y * s);
            w = *(const float2*)&Wih2[r * HID + 2 * p]; Wih2r[g][p] = pk(w.x * s, w.y * s);
            w = *(const float2*)&Whh2[r * HID + 2 * p]; Whh2r[g][p] = pk(w.x * s, w.y * s);
        }
    }
    u64 WL[5];
#pragma unroll
    for (int p = 0; p < 5; ++p) {
        float2 w = *(const float2*)&Wlin[2 * p];
        WL[p] = pk(w.x, w.y);
    }
    const float bl = __ldg(&blin[0]);

    // per-warp exchange buffers (12 floats per element slot, float4-aligned)
    __shared__ float4 s1[3][3];
    __shared__ float4 s2[3][3];

    // state
    u64 h1p[5], h2p[5];
#pragma unroll
    for (int p = 0; p < 5; ++p) { h1p[p] = 0ull; h2p[p] = 0ull; }
    float c1 = 0.0f, c2 = 0.0f, yprev = 0.0f;

    const float* xrow = x + (size_t)bc * T;
    float xcur = __ldg(&xrow[0]);

    for (int t = 0; t < TT; ++t) {
        // prefetch next x (off critical path)
        float xnext = 0.0f;
        if (t + 1 < T) xnext = __ldg(&xrow[t + 1]);
        const float xt = (t < T) ? xcur : yprev;

        // ---- layer 2, h2-dependent half first (independent of layer 1 chain) ----
        u64 a2[4];
#pragma unroll
        for (int g = 0; g < 4; ++g) {
            u64 a = pk(bias2[g], 0.0f);
#pragma unroll
            for (int p = 0; p < 5; ++p) a = ffma2(h2p[p], Whh2r[g][p], a);
            a2[g] = a;
        }

        // ---- layer 1 ----
        float gt1[4];
#pragma unroll
        for (int g = 0; g < 4; ++g) {
            u64 a = pk(fmaf(wx1[g], xt, bias1[g]), 0.0f);
#pragma unroll
            for (int p = 0; p < 5; ++p) a = ffma2(h1p[p], Whh1r[g][p], a);
            gt1[g] = hsum(a);
        }
        {
            const float si = sig_scaled(gt1[0]);
            const float sf = sig_scaled(gt1[1]);
            const float tg = tanh_scaled(gt1[2]);
            const float so = sig_scaled(gt1[3]);
            c1 = fmaf(sf, c1, si * tg);
            const float h1u = so * tanh_plain(c1);
            if (lane_ok) ((float*)&s1[ec][0])[u] = h1u;
        }
        __syncwarp();
        {
            float4 A = s1[ec][0], Bv = s1[ec][1], Cv = s1[ec][2];
            h1p[0] = pk(A.x, A.y);  h1p[1] = pk(A.z, A.w);
            h1p[2] = pk(Bv.x, Bv.y); h1p[3] = pk(Bv.z, Bv.w);
            h1p[4] = pk(Cv.x, Cv.y);
        }

        // ---- layer 2, h1-dependent half ----
        float gt2[4];
#pragma unroll
        for (int g = 0; g < 4; ++g) {
            u64 a = a2[g];
#pragma unroll
            for (int p = 0; p < 5; ++p) a = ffma2(h1p[p], Wih2r[g][p], a);
            gt2[g] = hsum(a);
        }
        {
            const float si = sig_scaled(gt2[0]);
            const float sf = sig_scaled(gt2[1]);
            const float tg = tanh_scaled(gt2[2]);
            const float so = sig_scaled(gt2[3]);
            c2 = fmaf(sf, c2, si * tg);
            const float h2u = so * tanh_plain(c2);
            if (lane_ok) ((float*)&s2[ec][0])[u] = h2u;
        }
        __syncwarp();
        {
            float4 A = s2[ec][0], Bv = s2[ec][1], Cv = s2[ec][2];
            h2p[0] = pk(A.x, A.y);  h2p[1] = pk(A.z, A.w);
            h2p[2] = pk(Bv.x, Bv.y); h2p[3] = pk(Bv.z, Bv.w);
            h2p[4] = pk(Cv.x, Cv.y);
        }

        // ---- y = h2 @ W_lin^T + b_lin ----
        u64 ya = pk(bl, 0.0f);
#pragma unroll
        for (int p = 0; p < 5; ++p) ya = ffma2(h2p[p], WL[p], ya);
        const float y = hsum(ya);

        if (b_ok && u == 0) out[(size_t)bc * TT + t] = y;
        yprev = y;
        xcur  = xnext;
    }
}

extern "C" void kernel_launch(void* const* d_in, const int* in_sizes, int n_in,
                              void* d_out, int out_size)
{
    const int B  = 2048;
    const int T  = in_sizes[0] / B;     // 1024
    const int TT = out_size / B;        // T + future = 1088

    const float* x    = (const float*)d_in[0];
    const float* Wih1 = (const float*)d_in[1];
    const float* Whh1 = (const float*)d_in[2];
    const float* bih1 = (const float*)d_in[3];
    const float* bhh1 = (const float*)d_in[4];
    const float* Wih2 = (const float*)d_in[5];
    const float* Whh2 = (const float*)d_in[6];
    const float* bih2 = (const float*)d_in[7];
    const float* bhh2 = (const float*)d_in[8];
    const float* Wlin = (const float*)d_in[9];
    const float* blin = (const float*)d_in[10];
    float* out = (float*)d_out;

    const int grid = (B + 2) / 3;       // 683 warps, 3 elements each
    lstm2_kernel<<<grid, 32>>>(x, Wih1, Whh1, bih1, bhh1,
                               Wih2, Whh2, bih2, bhh2,
                               Wlin, blin, out, B, T, TT);
}